// round 7
// baseline (speedup 1.0000x reference)
#include <cuda_runtime.h>
#include <cstdint>

#define NUM_NODE 50000
#define NUM_EDGE 1600000
#define NUM_REL  512
#define DIM      64
#define SCAN_T   1024

// ---------------------------------------------------------------------------
// Device scratch (alloc-free rule: __device__ globals)
// ---------------------------------------------------------------------------
__device__ int   g_count[NUM_NODE];
__device__ int   g_off[NUM_NODE + 1];
__device__ int   g_pos[NUM_EDGE];         // intra-bucket position per edge
__device__ int4  g_meta[NUM_EDGE];        // (u, r, w_bits, pad) per bucket slot
__device__ float g_u[NUM_NODE * DIM];     // sqrt-variance staged for GEMM

// ---------------------------------------------------------------------------
// K0: zero counters
// ---------------------------------------------------------------------------
__global__ void zero_kernel() {
    int i = blockIdx.x * blockDim.x + threadIdx.x;
    if (i < NUM_NODE) g_count[i] = 0;
}

// ---------------------------------------------------------------------------
// K1: histogram of destination nodes + record per-edge bucket position
// ---------------------------------------------------------------------------
__global__ void __launch_bounds__(256) hist_kernel(const int* __restrict__ edge_list) {
    int e = blockIdx.x * blockDim.x + threadIdx.x;
    if (e < NUM_EDGE) {
        int v = __ldg(&edge_list[e * 3 + 1]);
        g_pos[e] = atomicAdd(&g_count[v], 1);
    }
}

// ---------------------------------------------------------------------------
// K2: single-block exclusive scan over 50K counts -> offsets
// ---------------------------------------------------------------------------
__global__ void __launch_bounds__(SCAN_T) scan_kernel() {
    __shared__ int partial[SCAN_T];
    const int CH = (NUM_NODE + SCAN_T - 1) / SCAN_T;   // 49
    int t = threadIdx.x;
    int begin = t * CH;
    int endi  = min(begin + CH, NUM_NODE);

    int sum = 0;
    for (int i = begin; i < endi; i++) sum += g_count[i];
    partial[t] = sum;
    __syncthreads();

    #pragma unroll
    for (int off = 1; off < SCAN_T; off <<= 1) {
        int v = (t >= off) ? partial[t - off] : 0;
        __syncthreads();
        partial[t] += v;
        __syncthreads();
    }

    int base = (t == 0) ? 0 : partial[t - 1];
    for (int i = begin; i < endi; i++) {
        g_off[i] = base;
        base += g_count[i];
    }
    if (t == SCAN_T - 1) g_off[NUM_NODE] = partial[SCAN_T - 1];
}

// ---------------------------------------------------------------------------
// K3: scatter packed edge meta into buckets — 4 edges per thread,
// vectorized pos/weight loads, 4 independent store chains.
// ---------------------------------------------------------------------------
__global__ void __launch_bounds__(256) scatter_kernel(
    const int*   __restrict__ edge_list,
    const float* __restrict__ edge_weight)
{
    int t  = blockIdx.x * blockDim.x + threadIdx.x;
    int e0 = t * 4;
    if (e0 >= NUM_EDGE) return;

    if (e0 + 4 <= NUM_EDGE) {
        // edge_list rows e0..e0+3 = 12 consecutive ints = 3 int4s
        const int4* el = (const int4*)(edge_list + (size_t)e0 * 3);
        int4 c0 = __ldg(&el[0]);   // u0 v0 r0 u1
        int4 c1 = __ldg(&el[1]);   // v1 r1 u2 v2
        int4 c2 = __ldg(&el[2]);   // r2 u3 v3 r3
        int4   p = __ldg((const int4*)  (g_pos       + e0));
        float4 w = __ldg((const float4*)(edge_weight + e0));

        int s0 = __ldg(&g_off[c0.y]) + p.x;
        int s1 = __ldg(&g_off[c1.x]) + p.y;
        int s2 = __ldg(&g_off[c1.w]) + p.z;
        int s3 = __ldg(&g_off[c2.z]) + p.w;

        g_meta[s0] = make_int4(c0.x, c0.z, __float_as_int(w.x), 0);
        g_meta[s1] = make_int4(c0.w, c1.y, __float_as_int(w.y), 0);
        g_meta[s2] = make_int4(c1.z, c2.x, __float_as_int(w.z), 0);
        g_meta[s3] = make_int4(c2.y, c2.w, __float_as_int(w.w), 0);
    } else {
        for (int e = e0; e < NUM_EDGE; e++) {
            int   u = __ldg(&edge_list[e * 3 + 0]);
            int   v = __ldg(&edge_list[e * 3 + 1]);
            int   r = __ldg(&edge_list[e * 3 + 2]);
            float w = __ldg(&edge_weight[e]);
            int slot = __ldg(&g_off[v]) + g_pos[e];
            g_meta[slot] = make_int4(u, r, __float_as_int(w), 0);
        }
    }
}

// ---------------------------------------------------------------------------
// K4: per-node gather-reduce + variance, warp-per-node.
// Half-warps process alternating edges (2 edges in parallel), unrolled x4
// -> 8 edges / ~12 independent LDG.128 in flight per warp step.
// Cross-half combine via shfl_xor(16).
// ---------------------------------------------------------------------------
__global__ void __launch_bounds__(256) gather_kernel(
    const float* __restrict__ input,
    const float* __restrict__ boundary,
    const float* __restrict__ relw)
{
    int warp = (blockIdx.x * blockDim.x + threadIdx.x) >> 5;
    if (warp >= NUM_NODE) return;
    int n    = warp;
    int lane = threadIdx.x & 31;
    int g    = lane >> 4;        // which edge of the pair
    int sub  = lane & 15;        // float4 slice of the 64-dim row

    int start = __ldg(&g_off[n]);
    int end   = __ldg(&g_off[n + 1]);

    float4 s = make_float4(0.f, 0.f, 0.f, 0.f);
    float4 q = make_float4(0.f, 0.f, 0.f, 0.f);

    int j = start;

    // Main loop: 8 edges per warp iteration (4 per half-warp, interleaved)
    for (; j + 8 <= end; j += 8) {
        int e0 = j + g;
        int4 m0 = __ldg(&g_meta[e0 + 0]);
        int4 m1 = __ldg(&g_meta[e0 + 2]);
        int4 m2 = __ldg(&g_meta[e0 + 4]);
        int4 m3 = __ldg(&g_meta[e0 + 6]);

        float4 x0 = __ldg((const float4*)(input + (size_t)m0.x * DIM) + sub);
        float4 x1 = __ldg((const float4*)(input + (size_t)m1.x * DIM) + sub);
        float4 x2 = __ldg((const float4*)(input + (size_t)m2.x * DIM) + sub);
        float4 x3 = __ldg((const float4*)(input + (size_t)m3.x * DIM) + sub);

        float4 r0 = __ldg((const float4*)(relw + (size_t)m0.y * DIM) + sub);
        float4 r1 = __ldg((const float4*)(relw + (size_t)m1.y * DIM) + sub);
        float4 r2 = __ldg((const float4*)(relw + (size_t)m2.y * DIM) + sub);
        float4 r3 = __ldg((const float4*)(relw + (size_t)m3.y * DIM) + sub);

        float w0 = __int_as_float(m0.z);
        float w1 = __int_as_float(m1.z);
        float w2 = __int_as_float(m2.z);
        float w3 = __int_as_float(m3.z);

        float4 a0, a1, a2, a3;
        a0.x = x0.x * r0.x * w0; a0.y = x0.y * r0.y * w0;
        a0.z = x0.z * r0.z * w0; a0.w = x0.w * r0.w * w0;
        a1.x = x1.x * r1.x * w1; a1.y = x1.y * r1.y * w1;
        a1.z = x1.z * r1.z * w1; a1.w = x1.w * r1.w * w1;
        a2.x = x2.x * r2.x * w2; a2.y = x2.y * r2.y * w2;
        a2.z = x2.z * r2.z * w2; a2.w = x2.w * r2.w * w2;
        a3.x = x3.x * r3.x * w3; a3.y = x3.y * r3.y * w3;
        a3.z = x3.z * r3.z * w3; a3.w = x3.w * r3.w * w3;

        s.x += a0.x + a1.x + a2.x + a3.x;
        s.y += a0.y + a1.y + a2.y + a3.y;
        s.z += a0.z + a1.z + a2.z + a3.z;
        s.w += a0.w + a1.w + a2.w + a3.w;

        q.x += a0.x * a0.x + a1.x * a1.x + a2.x * a2.x + a3.x * a3.x;
        q.y += a0.y * a0.y + a1.y * a1.y + a2.y * a2.y + a3.y * a3.y;
        q.z += a0.z * a0.z + a1.z * a1.z + a2.z * a2.z + a3.z * a3.z;
        q.w += a0.w * a0.w + a1.w * a1.w + a2.w * a2.w + a3.w * a3.w;
    }

    // Pairwise remainder: 2 edges per iteration
    for (; j + 2 <= end; j += 2) {
        int4 m = __ldg(&g_meta[j + g]);
        float w   = __int_as_float(m.z);
        float4 x  = __ldg((const float4*)(input + (size_t)m.x * DIM) + sub);
        float4 rr = __ldg((const float4*)(relw  + (size_t)m.y * DIM) + sub);
        float4 a;
        a.x = x.x * rr.x * w; a.y = x.y * rr.y * w;
        a.z = x.z * rr.z * w; a.w = x.w * rr.w * w;
        s.x += a.x; s.y += a.y; s.z += a.z; s.w += a.w;
        q.x += a.x * a.x; q.y += a.y * a.y;
        q.z += a.z * a.z; q.w += a.w * a.w;
    }

    // Final odd edge: half-warp 0 only
    if (j < end && g == 0) {
        int4 m = __ldg(&g_meta[j]);
        float w   = __int_as_float(m.z);
        float4 x  = __ldg((const float4*)(input + (size_t)m.x * DIM) + sub);
        float4 rr = __ldg((const float4*)(relw  + (size_t)m.y * DIM) + sub);
        float4 a;
        a.x = x.x * rr.x * w; a.y = x.y * rr.y * w;
        a.z = x.z * rr.z * w; a.w = x.w * rr.w * w;
        s.x += a.x; s.y += a.y; s.z += a.z; s.w += a.w;
        q.x += a.x * a.x; q.y += a.y * a.y;
        q.z += a.z * a.z; q.w += a.w * a.w;
    }

    // Combine the two half-warps (same sub, different edge subset)
    s.x += __shfl_xor_sync(0xffffffffu, s.x, 16);
    s.y += __shfl_xor_sync(0xffffffffu, s.y, 16);
    s.z += __shfl_xor_sync(0xffffffffu, s.z, 16);
    s.w += __shfl_xor_sync(0xffffffffu, s.w, 16);
    q.x += __shfl_xor_sync(0xffffffffu, q.x, 16);
    q.y += __shfl_xor_sync(0xffffffffu, q.y, 16);
    q.z += __shfl_xor_sync(0xffffffffu, q.z, 16);
    q.w += __shfl_xor_sync(0xffffffffu, q.w, 16);

    if (g == 0) {
        float4 bb = __ldg((const float4*)(boundary + (size_t)n * DIM) + sub);
        s.x += bb.x; s.y += bb.y; s.z += bb.z; s.w += bb.w;
        q.x += bb.x * bb.x; q.y += bb.y * bb.y;
        q.z += bb.z * bb.z; q.w += bb.w * bb.w;

        float deg = (float)(end - start);
        float inv = 1.0f / (deg + 1.0f);

        float4 u4;
        float sm;
        sm = s.x * inv; u4.x = sqrtf(fmaxf(q.x * inv - sm * sm, 1e-6f));
        sm = s.y * inv; u4.y = sqrtf(fmaxf(q.y * inv - sm * sm, 1e-6f));
        sm = s.z * inv; u4.z = sqrtf(fmaxf(q.z * inv - sm * sm, 1e-6f));
        sm = s.w * inv; u4.w = sqrtf(fmaxf(q.w * inv - sm * sm, 1e-6f));

        *((float4*)(g_u + (size_t)n * DIM) + sub) = u4;
    }
}

// ---------------------------------------------------------------------------
// K5: 64x64 GEMM epilogue: out = u @ W^T + b
// ---------------------------------------------------------------------------
__global__ void __launch_bounds__(256) gemm_kernel(
    const float* __restrict__ W,
    const float* __restrict__ b,
    float* __restrict__ out)
{
    __shared__ float Wsh[DIM * DIM];         // Wsh[d*64 + j] = W[j*64 + d]
    __shared__ float Ush[64 * (DIM + 1)];    // padded stride 65
    __shared__ float bsh[DIM];

    int tid = threadIdx.x;

    for (int i = tid; i < DIM * DIM; i += 256) {
        int j = i >> 6, d = i & 63;
        Wsh[d * DIM + j] = W[i];
    }
    if (tid < DIM) bsh[tid] = b[tid];

    int n0 = blockIdx.x * 64;

    for (int i = tid; i < 64 * DIM; i += 256) {
        int nl = i >> 6, d = i & 63;
        int n  = n0 + nl;
        float u = (n < NUM_NODE) ? g_u[(size_t)n0 * DIM + i] : 0.0f;
        Ush[nl * (DIM + 1) + d] = u;
    }
    __syncthreads();

    int nl = tid >> 2;
    int j0 = (tid & 3) * 16;

    float acc[16];
    #pragma unroll
    for (int k = 0; k < 16; k++) acc[k] = bsh[j0 + k];

    #pragma unroll 4
    for (int d = 0; d < DIM; d++) {
        float u = Ush[nl * (DIM + 1) + d];
        const float4* wrow = (const float4*)&Wsh[d * DIM + j0];
        float4 w0 = wrow[0];
        float4 w1 = wrow[1];
        float4 w2 = wrow[2];
        float4 w3 = wrow[3];
        acc[0]  += u * w0.x;  acc[1]  += u * w0.y;
        acc[2]  += u * w0.z;  acc[3]  += u * w0.w;
        acc[4]  += u * w1.x;  acc[5]  += u * w1.y;
        acc[6]  += u * w1.z;  acc[7]  += u * w1.w;
        acc[8]  += u * w2.x;  acc[9]  += u * w2.y;
        acc[10] += u * w2.z;  acc[11] += u * w2.w;
        acc[12] += u * w3.x;  acc[13] += u * w3.y;
        acc[14] += u * w3.z;  acc[15] += u * w3.w;
    }

    int n = n0 + nl;
    if (n < NUM_NODE) {
        float4* op = (float4*)(out + (size_t)n * DIM + j0);
        op[0] = make_float4(acc[0],  acc[1],  acc[2],  acc[3]);
        op[1] = make_float4(acc[4],  acc[5],  acc[6],  acc[7]);
        op[2] = make_float4(acc[8],  acc[9],  acc[10], acc[11]);
        op[3] = make_float4(acc[12], acc[13], acc[14], acc[15]);
    }
}

// ---------------------------------------------------------------------------
// Launch
// Inputs (metadata order): input, boundary, edge_list, edge_weight,
//                          relation_weight, W, b
// ---------------------------------------------------------------------------
extern "C" void kernel_launch(void* const* d_in, const int* in_sizes, int n_in,
                              void* d_out, int out_size)
{
    const float* input    = (const float*)d_in[0];
    const float* boundary = (const float*)d_in[1];
    const int*   edges    = (const int*)  d_in[2];
    const float* eweight  = (const float*)d_in[3];
    const float* relw     = (const float*)d_in[4];
    const float* W        = (const float*)d_in[5];
    const float* b        = (const float*)d_in[6];
    float*       out      = (float*)d_out;

    zero_kernel<<<(NUM_NODE + 255) / 256, 256>>>();
    hist_kernel<<<(NUM_EDGE + 255) / 256, 256>>>(edges);
    scan_kernel<<<1, SCAN_T>>>();
    scatter_kernel<<<((NUM_EDGE + 3) / 4 + 255) / 256, 256>>>(edges, eweight);

    // warp per node: 8 nodes per 256-thread block
    gather_kernel<<<(NUM_NODE * 32 + 255) / 256, 256>>>(input, boundary, relw);
    gemm_kernel<<<(NUM_NODE + 63) / 64, 256>>>(W, b, out);
}

// round 12
// speedup vs baseline: 1.0045x; 1.0045x over previous
#include <cuda_runtime.h>
#include <cstdint>

#define NUM_NODE 50000
#define NUM_EDGE 1600000
#define NUM_REL  512
#define DIM      64
#define SCAN_T   1024

// ---------------------------------------------------------------------------
// Device scratch (alloc-free rule: __device__ globals).
// g_count is zero-initialized at module load and re-zeroed by gather_gemm
// at the end of every call, so each kernel_launch sees zeroed counters.
// ---------------------------------------------------------------------------
__device__ int   g_count[NUM_NODE];
__device__ int   g_off[NUM_NODE + 1];
__device__ int   g_pos[NUM_EDGE];         // intra-bucket position per edge
__device__ int4  g_meta[NUM_EDGE];        // (u, r, w_bits, pad) per bucket slot

// ---------------------------------------------------------------------------
// K1: histogram of destination nodes + record per-edge bucket position.
// 4 edges per thread, vectorized int4 loads of edge_list, int4 store of pos.
// ---------------------------------------------------------------------------
__global__ void __launch_bounds__(256) hist_kernel(const int* __restrict__ edge_list) {
    int t  = blockIdx.x * blockDim.x + threadIdx.x;
    int e0 = t * 4;
    if (e0 >= NUM_EDGE) return;

    if (e0 + 4 <= NUM_EDGE) {
        const int4* el = (const int4*)(edge_list + (size_t)e0 * 3);
        int4 c0 = __ldg(&el[0]);   // u0 v0 r0 u1
        int4 c1 = __ldg(&el[1]);   // v1 r1 u2 v2
        int4 c2 = __ldg(&el[2]);   // r2 u3 v3 r3
        int4 p;
        p.x = atomicAdd(&g_count[c0.y], 1);
        p.y = atomicAdd(&g_count[c1.x], 1);
        p.z = atomicAdd(&g_count[c1.w], 1);
        p.w = atomicAdd(&g_count[c2.z], 1);
        *((int4*)(g_pos + e0)) = p;
    } else {
        for (int e = e0; e < NUM_EDGE; e++) {
            int v = __ldg(&edge_list[e * 3 + 1]);
            g_pos[e] = atomicAdd(&g_count[v], 1);
        }
    }
}

// ---------------------------------------------------------------------------
// K2: single-block exclusive scan over 50K counts -> offsets
// ---------------------------------------------------------------------------
__global__ void __launch_bounds__(SCAN_T) scan_kernel() {
    __shared__ int partial[SCAN_T];
    const int CH = (NUM_NODE + SCAN_T - 1) / SCAN_T;   // 49
    int t = threadIdx.x;
    int begin = t * CH;
    int endi  = min(begin + CH, NUM_NODE);

    int sum = 0;
    for (int i = begin; i < endi; i++) sum += g_count[i];
    partial[t] = sum;
    __syncthreads();

    #pragma unroll
    for (int off = 1; off < SCAN_T; off <<= 1) {
        int v = (t >= off) ? partial[t - off] : 0;
        __syncthreads();
        partial[t] += v;
        __syncthreads();
    }

    int base = (t == 0) ? 0 : partial[t - 1];
    for (int i = begin; i < endi; i++) {
        g_off[i] = base;
        base += g_count[i];
    }
    if (t == SCAN_T - 1) g_off[NUM_NODE] = partial[SCAN_T - 1];
}

// ---------------------------------------------------------------------------
// K3: scatter packed edge meta into buckets — atomic-free
// ---------------------------------------------------------------------------
__global__ void __launch_bounds__(256) scatter_kernel(
    const int*   __restrict__ edge_list,
    const float* __restrict__ edge_weight)
{
    int e = blockIdx.x * blockDim.x + threadIdx.x;
    if (e < NUM_EDGE) {
        int   u   = __ldg(&edge_list[e * 3 + 0]);
        int   v   = __ldg(&edge_list[e * 3 + 1]);
        int   r   = __ldg(&edge_list[e * 3 + 2]);
        float w   = __ldg(&edge_weight[e]);
        int   pos = __ldg(&g_pos[e]);
        int  slot = __ldg(&g_off[v]) + pos;
        g_meta[slot] = make_int4(u, r, __float_as_int(w), 0);
    }
}

// ---------------------------------------------------------------------------
// K4: fused gather-reduce + variance + 64x64 GEMM.
// Block = 256 threads (8 warps) handles a tile of 64 nodes:
//   phase 1: warp-per-node gather (8 rounds), u staged into shared
//   phase 2: register-blocked GEMM out = u @ W^T + b
// Also re-zeroes g_count for the next call.
// ---------------------------------------------------------------------------
__global__ void __launch_bounds__(256) gather_gemm_kernel(
    const float* __restrict__ input,
    const float* __restrict__ boundary,
    const float* __restrict__ relw,
    const float* __restrict__ W,
    const float* __restrict__ b,
    float* __restrict__ out)
{
    __shared__ float Wsh[DIM * DIM];    // Wsh[d*64 + j] = W[j*64 + d]
    __shared__ float Ush[64 * 68];      // stride 68 (float4-aligned, conflict-free)
    __shared__ float bsh[DIM];

    int tid  = threadIdx.x;
    int wid  = tid >> 5;
    int lane = tid & 31;
    int g    = lane >> 4;       // which edge of the pair
    int sub  = lane & 15;       // float4 slice of the 64-dim row
    int n0   = blockIdx.x * 64;

    // Load W transposed + bias while gather proceeds
    for (int i = tid; i < DIM * DIM; i += 256) {
        int j = i >> 6, d = i & 63;
        Wsh[d * DIM + j] = W[i];
    }
    if (tid < DIM) bsh[tid] = b[tid];

    // ---- Phase 1: gather, 8 nodes per warp ----
    #pragma unroll 1
    for (int k = 0; k < 8; k++) {
        int nl = (k << 3) + wid;        // node within tile
        int n  = n0 + nl;
        if (n >= NUM_NODE) continue;

        int start = __ldg(&g_off[n]);
        int end   = __ldg(&g_off[n + 1]);

        if (lane == 0) g_count[n] = 0;   // self-clean for next call

        float4 s = make_float4(0.f, 0.f, 0.f, 0.f);
        float4 q = make_float4(0.f, 0.f, 0.f, 0.f);

        int j = start;
        for (; j + 8 <= end; j += 8) {
            int e0 = j + g;
            int4 m0 = __ldg(&g_meta[e0 + 0]);
            int4 m1 = __ldg(&g_meta[e0 + 2]);
            int4 m2 = __ldg(&g_meta[e0 + 4]);
            int4 m3 = __ldg(&g_meta[e0 + 6]);

            float4 x0 = __ldg((const float4*)(input + (size_t)m0.x * DIM) + sub);
            float4 x1 = __ldg((const float4*)(input + (size_t)m1.x * DIM) + sub);
            float4 x2 = __ldg((const float4*)(input + (size_t)m2.x * DIM) + sub);
            float4 x3 = __ldg((const float4*)(input + (size_t)m3.x * DIM) + sub);

            float4 r0 = __ldg((const float4*)(relw + (size_t)m0.y * DIM) + sub);
            float4 r1 = __ldg((const float4*)(relw + (size_t)m1.y * DIM) + sub);
            float4 r2 = __ldg((const float4*)(relw + (size_t)m2.y * DIM) + sub);
            float4 r3 = __ldg((const float4*)(relw + (size_t)m3.y * DIM) + sub);

            float w0 = __int_as_float(m0.z);
            float w1 = __int_as_float(m1.z);
            float w2 = __int_as_float(m2.z);
            float w3 = __int_as_float(m3.z);

            float4 a0, a1, a2, a3;
            a0.x = x0.x * r0.x * w0; a0.y = x0.y * r0.y * w0;
            a0.z = x0.z * r0.z * w0; a0.w = x0.w * r0.w * w0;
            a1.x = x1.x * r1.x * w1; a1.y = x1.y * r1.y * w1;
            a1.z = x1.z * r1.z * w1; a1.w = x1.w * r1.w * w1;
            a2.x = x2.x * r2.x * w2; a2.y = x2.y * r2.y * w2;
            a2.z = x2.z * r2.z * w2; a2.w = x2.w * r2.w * w2;
            a3.x = x3.x * r3.x * w3; a3.y = x3.y * r3.y * w3;
            a3.z = x3.z * r3.z * w3; a3.w = x3.w * r3.w * w3;

            s.x += a0.x + a1.x + a2.x + a3.x;
            s.y += a0.y + a1.y + a2.y + a3.y;
            s.z += a0.z + a1.z + a2.z + a3.z;
            s.w += a0.w + a1.w + a2.w + a3.w;

            q.x += a0.x * a0.x + a1.x * a1.x + a2.x * a2.x + a3.x * a3.x;
            q.y += a0.y * a0.y + a1.y * a1.y + a2.y * a2.y + a3.y * a3.y;
            q.z += a0.z * a0.z + a1.z * a1.z + a2.z * a2.z + a3.z * a3.z;
            q.w += a0.w * a0.w + a1.w * a1.w + a2.w * a2.w + a3.w * a3.w;
        }

        for (; j + 2 <= end; j += 2) {
            int4 m = __ldg(&g_meta[j + g]);
            float w   = __int_as_float(m.z);
            float4 x  = __ldg((const float4*)(input + (size_t)m.x * DIM) + sub);
            float4 rr = __ldg((const float4*)(relw  + (size_t)m.y * DIM) + sub);
            float4 a;
            a.x = x.x * rr.x * w; a.y = x.y * rr.y * w;
            a.z = x.z * rr.z * w; a.w = x.w * rr.w * w;
            s.x += a.x; s.y += a.y; s.z += a.z; s.w += a.w;
            q.x += a.x * a.x; q.y += a.y * a.y;
            q.z += a.z * a.z; q.w += a.w * a.w;
        }

        if (j < end && g == 0) {
            int4 m = __ldg(&g_meta[j]);
            float w   = __int_as_float(m.z);
            float4 x  = __ldg((const float4*)(input + (size_t)m.x * DIM) + sub);
            float4 rr = __ldg((const float4*)(relw  + (size_t)m.y * DIM) + sub);
            float4 a;
            a.x = x.x * rr.x * w; a.y = x.y * rr.y * w;
            a.z = x.z * rr.z * w; a.w = x.w * rr.w * w;
            s.x += a.x; s.y += a.y; s.z += a.z; s.w += a.w;
            q.x += a.x * a.x; q.y += a.y * a.y;
            q.z += a.z * a.z; q.w += a.w * a.w;
        }

        // Combine half-warps
        s.x += __shfl_xor_sync(0xffffffffu, s.x, 16);
        s.y += __shfl_xor_sync(0xffffffffu, s.y, 16);
        s.z += __shfl_xor_sync(0xffffffffu, s.z, 16);
        s.w += __shfl_xor_sync(0xffffffffu, s.w, 16);
        q.x += __shfl_xor_sync(0xffffffffu, q.x, 16);
        q.y += __shfl_xor_sync(0xffffffffu, q.y, 16);
        q.z += __shfl_xor_sync(0xffffffffu, q.z, 16);
        q.w += __shfl_xor_sync(0xffffffffu, q.w, 16);

        if (g == 0) {
            float4 bb = __ldg((const float4*)(boundary + (size_t)n * DIM) + sub);
            s.x += bb.x; s.y += bb.y; s.z += bb.z; s.w += bb.w;
            q.x += bb.x * bb.x; q.y += bb.y * bb.y;
            q.z += bb.z * bb.z; q.w += bb.w * bb.w;

            float deg = (float)(end - start);
            float inv = 1.0f / (deg + 1.0f);

            float sm;
            float* urow = &Ush[nl * 68 + sub * 4];
            sm = s.x * inv; urow[0] = sqrtf(fmaxf(q.x * inv - sm * sm, 1e-6f));
            sm = s.y * inv; urow[1] = sqrtf(fmaxf(q.y * inv - sm * sm, 1e-6f));
            sm = s.z * inv; urow[2] = sqrtf(fmaxf(q.z * inv - sm * sm, 1e-6f));
            sm = s.w * inv; urow[3] = sqrtf(fmaxf(q.w * inv - sm * sm, 1e-6f));
        }
    }
    __syncthreads();

    // ---- Phase 2: GEMM out = u @ W^T + b ----
    int nl = tid >> 2;
    int j0 = (tid & 3) * 16;

    float acc[16];
    #pragma unroll
    for (int k = 0; k < 16; k++) acc[k] = bsh[j0 + k];

    #pragma unroll 4
    for (int d = 0; d < DIM; d++) {
        float u = Ush[nl * 68 + d];
        const float4* wrow = (const float4*)&Wsh[d * DIM + j0];
        float4 w0 = wrow[0];
        float4 w1 = wrow[1];
        float4 w2 = wrow[2];
        float4 w3 = wrow[3];
        acc[0]  += u * w0.x;  acc[1]  += u * w0.y;
        acc[2]  += u * w0.z;  acc[3]  += u * w0.w;
        acc[4]  += u * w1.x;  acc[5]  += u * w1.y;
        acc[6]  += u * w1.z;  acc[7]  += u * w1.w;
        acc[8]  += u * w2.x;  acc[9]  += u * w2.y;
        acc[10] += u * w2.z;  acc[11] += u * w2.w;
        acc[12] += u * w3.x;  acc[13] += u * w3.y;
        acc[14] += u * w3.z;  acc[15] += u * w3.w;
    }

    int n = n0 + nl;
    if (n < NUM_NODE) {
        float4* op = (float4*)(out + (size_t)n * DIM + j0);
        op[0] = make_float4(acc[0],  acc[1],  acc[2],  acc[3]);
        op[1] = make_float4(acc[4],  acc[5],  acc[6],  acc[7]);
        op[2] = make_float4(acc[8],  acc[9],  acc[10], acc[11]);
        op[3] = make_float4(acc[12], acc[13], acc[14], acc[15]);
    }
}

// ---------------------------------------------------------------------------
// Launch
// Inputs (metadata order): input, boundary, edge_list, edge_weight,
//                          relation_weight, W, b
// ---------------------------------------------------------------------------
extern "C" void kernel_launch(void* const* d_in, const int* in_sizes, int n_in,
                              void* d_out, int out_size)
{
    const float* input    = (const float*)d_in[0];
    const float* boundary = (const float*)d_in[1];
    const int*   edges    = (const int*)  d_in[2];
    const float* eweight  = (const float*)d_in[3];
    const float* relw     = (const float*)d_in[4];
    const float* W        = (const float*)d_in[5];
    const float* b        = (const float*)d_in[6];
    float*       out      = (float*)d_out;

    hist_kernel<<<((NUM_EDGE + 3) / 4 + 255) / 256, 256>>>(edges);
    scan_kernel<<<1, SCAN_T>>>();
    scatter_kernel<<<(NUM_EDGE + 255) / 256, 256>>>(edges, eweight);
    gather_gemm_kernel<<<(NUM_NODE + 63) / 64, 256>>>(
        input, boundary, relw, W, b, out);
}

// round 15
// speedup vs baseline: 1.2441x; 1.2386x over previous
#include <cuda_runtime.h>
#include <cstdint>

#define NUM_NODE 50000
#define NUM_EDGE 1600000
#define NUM_REL  512
#define DIM      64
#define SCAN_T   1024

// ---------------------------------------------------------------------------
// Device scratch (alloc-free rule: __device__ globals).
// g_count is zero-initialized at module load and re-zeroed by gather_gemm
// at the end of every call, so each kernel_launch sees zeroed counters.
// ---------------------------------------------------------------------------
__device__ int   g_count[NUM_NODE];
__device__ int   g_off[NUM_NODE + 1];
__device__ int   g_pos[NUM_EDGE];         // intra-bucket position per edge
__device__ int2  g_meta[NUM_EDGE];        // (u | r<<16, w_bits) per bucket slot

// ---------------------------------------------------------------------------
// K1: histogram of destination nodes + record per-edge bucket position.
// 4 edges per thread, vectorized int4 loads of edge_list, int4 store of pos.
// ---------------------------------------------------------------------------
__global__ void __launch_bounds__(256) hist_kernel(const int* __restrict__ edge_list) {
    int t  = blockIdx.x * blockDim.x + threadIdx.x;
    int e0 = t * 4;
    if (e0 >= NUM_EDGE) return;

    if (e0 + 4 <= NUM_EDGE) {
        const int4* el = (const int4*)(edge_list + (size_t)e0 * 3);
        int4 c0 = __ldg(&el[0]);   // u0 v0 r0 u1
        int4 c1 = __ldg(&el[1]);   // v1 r1 u2 v2
        int4 c2 = __ldg(&el[2]);   // r2 u3 v3 r3
        int4 p;
        p.x = atomicAdd(&g_count[c0.y], 1);
        p.y = atomicAdd(&g_count[c1.x], 1);
        p.z = atomicAdd(&g_count[c1.w], 1);
        p.w = atomicAdd(&g_count[c2.z], 1);
        *((int4*)(g_pos + e0)) = p;
    } else {
        for (int e = e0; e < NUM_EDGE; e++) {
            int v = __ldg(&edge_list[e * 3 + 1]);
            g_pos[e] = atomicAdd(&g_count[v], 1);
        }
    }
}

// ---------------------------------------------------------------------------
// K2: single-block exclusive scan, warp-coalesced two-pass.
// Warp w owns contiguous node range [w*CHW, (w+1)*CHW); all its global
// accesses are coalesced 32-wide; prefix via shfl warp scans.
// ---------------------------------------------------------------------------
__global__ void __launch_bounds__(SCAN_T) scan_kernel() {
    __shared__ int wsum[32];
    int t    = threadIdx.x;
    int wid  = t >> 5;
    int lane = t & 31;
    const int CHW = (NUM_NODE + 31) / 32;   // 1563 nodes per warp
    int base = wid * CHW;
    int end  = min(base + CHW, NUM_NODE);

    // Pass 1: warp totals (coalesced strided reads)
    int sum = 0;
    for (int i = base + lane; i < end; i += 32) sum += g_count[i];
    #pragma unroll
    for (int o = 16; o > 0; o >>= 1) sum += __shfl_xor_sync(0xffffffffu, sum, o);
    if (lane == 0) wsum[wid] = sum;
    __syncthreads();

    // Exclusive scan of the 32 warp totals (warp 0)
    if (wid == 0) {
        int v    = wsum[lane];
        int incl = v;
        #pragma unroll
        for (int o = 1; o < 32; o <<= 1) {
            int p = __shfl_up_sync(0xffffffffu, incl, o);
            if (lane >= o) incl += p;
        }
        wsum[lane] = incl - v;
        if (lane == 31) g_off[NUM_NODE] = incl;
    }
    __syncthreads();

    // Pass 2: write offsets, 32 nodes per round, coalesced
    int run = wsum[wid];
    for (int i0 = base; i0 < end; i0 += 32) {
        int i = i0 + lane;
        int c = (i < end) ? g_count[i] : 0;
        int incl = c;
        #pragma unroll
        for (int o = 1; o < 32; o <<= 1) {
            int p = __shfl_up_sync(0xffffffffu, incl, o);
            if (lane >= o) incl += p;
        }
        if (i < end) g_off[i] = run + incl - c;
        run += __shfl_sync(0xffffffffu, incl, 31);
    }
}

// ---------------------------------------------------------------------------
// K3: scatter packed edge meta into buckets — atomic-free, int2 (8B) payload
// ---------------------------------------------------------------------------
__global__ void __launch_bounds__(256) scatter_kernel(
    const int*   __restrict__ edge_list,
    const float* __restrict__ edge_weight)
{
    int e = blockIdx.x * blockDim.x + threadIdx.x;
    if (e < NUM_EDGE) {
        int   u   = __ldg(&edge_list[e * 3 + 0]);
        int   v   = __ldg(&edge_list[e * 3 + 1]);
        int   r   = __ldg(&edge_list[e * 3 + 2]);
        float w   = __ldg(&edge_weight[e]);
        int   pos = __ldg(&g_pos[e]);
        int  slot = __ldg(&g_off[v]) + pos;
        g_meta[slot] = make_int2(u | (r << 16), __float_as_int(w));
    }
}

// ---------------------------------------------------------------------------
// K4: fused gather-reduce + variance + 64x64 GEMM.
// Warp-per-node, half-warp edge pairs, x4 unroll, and SOFTWARE-PIPELINED
// meta loads: metas for batch i+1 are fetched while batch i's x/rel loads
// are outstanding, breaking the meta->data latency chain.
// ---------------------------------------------------------------------------
__global__ void __launch_bounds__(256) gather_gemm_kernel(
    const float* __restrict__ input,
    const float* __restrict__ boundary,
    const float* __restrict__ relw,
    const float* __restrict__ W,
    const float* __restrict__ b,
    float* __restrict__ out)
{
    __shared__ float Wsh[DIM * DIM];    // Wsh[d*64 + j] = W[j*64 + d]
    __shared__ float Ush[64 * 68];      // stride 68 (float4-aligned, conflict-free)
    __shared__ float bsh[DIM];

    int tid  = threadIdx.x;
    int wid  = tid >> 5;
    int lane = tid & 31;
    int g    = lane >> 4;       // which edge of the pair
    int sub  = lane & 15;       // float4 slice of the 64-dim row
    int n0   = blockIdx.x * 64;

    for (int i = tid; i < DIM * DIM; i += 256) {
        int j = i >> 6, d = i & 63;
        Wsh[d * DIM + j] = W[i];
    }
    if (tid < DIM) bsh[tid] = b[tid];

    // ---- Phase 1: gather, 8 nodes per warp ----
    #pragma unroll 1
    for (int k = 0; k < 8; k++) {
        int nl = (k << 3) + wid;
        int n  = n0 + nl;
        if (n >= NUM_NODE) continue;

        int start = __ldg(&g_off[n]);
        int end   = __ldg(&g_off[n + 1]);

        if (lane == 0) g_count[n] = 0;   // self-clean for next call

        float4 s = make_float4(0.f, 0.f, 0.f, 0.f);
        float4 q = make_float4(0.f, 0.f, 0.f, 0.f);

        int j    = start;
        int lim8 = end - 8;

        if (j <= lim8) {
            // Prime the meta pipeline
            int e0 = j + g;
            int2 m0 = __ldg(&g_meta[e0 + 0]);
            int2 m1 = __ldg(&g_meta[e0 + 2]);
            int2 m2 = __ldg(&g_meta[e0 + 4]);
            int2 m3 = __ldg(&g_meta[e0 + 6]);

            #pragma unroll 1
            for (; j <= lim8; j += 8) {
                // Issue data loads for the current metas immediately
                float4 x0 = __ldg((const float4*)(input + (size_t)(m0.x & 0xFFFF) * DIM) + sub);
                float4 x1 = __ldg((const float4*)(input + (size_t)(m1.x & 0xFFFF) * DIM) + sub);
                float4 x2 = __ldg((const float4*)(input + (size_t)(m2.x & 0xFFFF) * DIM) + sub);
                float4 x3 = __ldg((const float4*)(input + (size_t)(m3.x & 0xFFFF) * DIM) + sub);

                float4 r0 = __ldg((const float4*)(relw + (size_t)(m0.x >> 16) * DIM) + sub);
                float4 r1 = __ldg((const float4*)(relw + (size_t)(m1.x >> 16) * DIM) + sub);
                float4 r2 = __ldg((const float4*)(relw + (size_t)(m2.x >> 16) * DIM) + sub);
                float4 r3 = __ldg((const float4*)(relw + (size_t)(m3.x >> 16) * DIM) + sub);

                // Prefetch next batch's metas while data loads are in flight
                int jp = (j + 8 <= lim8) ? (j + 8) : j;
                int e1 = jp + g;
                int2 t0 = __ldg(&g_meta[e1 + 0]);
                int2 t1 = __ldg(&g_meta[e1 + 2]);
                int2 t2 = __ldg(&g_meta[e1 + 4]);
                int2 t3 = __ldg(&g_meta[e1 + 6]);

                float w0 = __int_as_float(m0.y);
                float w1 = __int_as_float(m1.y);
                float w2 = __int_as_float(m2.y);
                float w3 = __int_as_float(m3.y);

                float4 a0, a1, a2, a3;
                a0.x = x0.x * r0.x * w0; a0.y = x0.y * r0.y * w0;
                a0.z = x0.z * r0.z * w0; a0.w = x0.w * r0.w * w0;
                a1.x = x1.x * r1.x * w1; a1.y = x1.y * r1.y * w1;
                a1.z = x1.z * r1.z * w1; a1.w = x1.w * r1.w * w1;
                a2.x = x2.x * r2.x * w2; a2.y = x2.y * r2.y * w2;
                a2.z = x2.z * r2.z * w2; a2.w = x2.w * r2.w * w2;
                a3.x = x3.x * r3.x * w3; a3.y = x3.y * r3.y * w3;
                a3.z = x3.z * r3.z * w3; a3.w = x3.w * r3.w * w3;

                s.x += a0.x + a1.x + a2.x + a3.x;
                s.y += a0.y + a1.y + a2.y + a3.y;
                s.z += a0.z + a1.z + a2.z + a3.z;
                s.w += a0.w + a1.w + a2.w + a3.w;

                q.x += a0.x * a0.x + a1.x * a1.x + a2.x * a2.x + a3.x * a3.x;
                q.y += a0.y * a0.y + a1.y * a1.y + a2.y * a2.y + a3.y * a3.y;
                q.z += a0.z * a0.z + a1.z * a1.z + a2.z * a2.z + a3.z * a3.z;
                q.w += a0.w * a0.w + a1.w * a1.w + a2.w * a2.w + a3.w * a3.w;

                m0 = t0; m1 = t1; m2 = t2; m3 = t3;
            }
        }

        // Pairwise remainder: 2 edges per iteration
        for (; j + 2 <= end; j += 2) {
            int2 m = __ldg(&g_meta[j + g]);
            float w   = __int_as_float(m.y);
            float4 x  = __ldg((const float4*)(input + (size_t)(m.x & 0xFFFF) * DIM) + sub);
            float4 rr = __ldg((const float4*)(relw  + (size_t)(m.x >> 16) * DIM) + sub);
            float4 a;
            a.x = x.x * rr.x * w; a.y = x.y * rr.y * w;
            a.z = x.z * rr.z * w; a.w = x.w * rr.w * w;
            s.x += a.x; s.y += a.y; s.z += a.z; s.w += a.w;
            q.x += a.x * a.x; q.y += a.y * a.y;
            q.z += a.z * a.z; q.w += a.w * a.w;
        }

        // Final odd edge: half-warp 0 only
        if (j < end && g == 0) {
            int2 m = __ldg(&g_meta[j]);
            float w   = __int_as_float(m.y);
            float4 x  = __ldg((const float4*)(input + (size_t)(m.x & 0xFFFF) * DIM) + sub);
            float4 rr = __ldg((const float4*)(relw  + (size_t)(m.x >> 16) * DIM) + sub);
            float4 a;
            a.x = x.x * rr.x * w; a.y = x.y * rr.y * w;
            a.z = x.z * rr.z * w; a.w = x.w * rr.w * w;
            s.x += a.x; s.y += a.y; s.z += a.z; s.w += a.w;
            q.x += a.x * a.x; q.y += a.y * a.y;
            q.z += a.z * a.z; q.w += a.w * a.w;
        }

        // Combine half-warps
        s.x += __shfl_xor_sync(0xffffffffu, s.x, 16);
        s.y += __shfl_xor_sync(0xffffffffu, s.y, 16);
        s.z += __shfl_xor_sync(0xffffffffu, s.z, 16);
        s.w += __shfl_xor_sync(0xffffffffu, s.w, 16);
        q.x += __shfl_xor_sync(0xffffffffu, q.x, 16);
        q.y += __shfl_xor_sync(0xffffffffu, q.y, 16);
        q.z += __shfl_xor_sync(0xffffffffu, q.z, 16);
        q.w += __shfl_xor_sync(0xffffffffu, q.w, 16);

        if (g == 0) {
            float4 bb = __ldg((const float4*)(boundary + (size_t)n * DIM) + sub);
            s.x += bb.x; s.y += bb.y; s.z += bb.z; s.w += bb.w;
            q.x += bb.x * bb.x; q.y += bb.y * bb.y;
            q.z += bb.z * bb.z; q.w += bb.w * bb.w;

            float deg = (float)(end - start);
            float inv = 1.0f / (deg + 1.0f);

            float sm;
            float* urow = &Ush[nl * 68 + sub * 4];
            sm = s.x * inv; urow[0] = sqrtf(fmaxf(q.x * inv - sm * sm, 1e-6f));
            sm = s.y * inv; urow[1] = sqrtf(fmaxf(q.y * inv - sm * sm, 1e-6f));
            sm = s.z * inv; urow[2] = sqrtf(fmaxf(q.z * inv - sm * sm, 1e-6f));
            sm = s.w * inv; urow[3] = sqrtf(fmaxf(q.w * inv - sm * sm, 1e-6f));
        }
    }
    __syncthreads();

    // ---- Phase 2: GEMM out = u @ W^T + b ----
    int nl = tid >> 2;
    int j0 = (tid & 3) * 16;

    float acc[16];
    #pragma unroll
    for (int k = 0; k < 16; k++) acc[k] = bsh[j0 + k];

    #pragma unroll 4
    for (int d = 0; d < DIM; d++) {
        float u = Ush[nl * 68 + d];
        const float4* wrow = (const float4*)&Wsh[d * DIM + j0];
        float4 w0 = wrow[0];
        float4 w1 = wrow[1];
        float4 w2 = wrow[2];
        float4 w3 = wrow[3];
        acc[0]  += u * w0.x;  acc[1]  += u * w0.y;
        acc[2]  += u * w0.z;  acc[3]  += u * w0.w;
        acc[4]  += u * w1.x;  acc[5]  += u * w1.y;
        acc[6]  += u * w1.z;  acc[7]  += u * w1.w;
        acc[8]  += u * w2.x;  acc[9]  += u * w2.y;
        acc[10] += u * w2.z;  acc[11] += u * w2.w;
        acc[12] += u * w3.x;  acc[13] += u * w3.y;
        acc[14] += u * w3.z;  acc[15] += u * w3.w;
    }

    int n = n0 + nl;
    if (n < NUM_NODE) {
        float4* op = (float4*)(out + (size_t)n * DIM + j0);
        op[0] = make_float4(acc[0],  acc[1],  acc[2],  acc[3]);
        op[1] = make_float4(acc[4],  acc[5],  acc[6],  acc[7]);
        op[2] = make_float4(acc[8],  acc[9],  acc[10], acc[11]);
        op[3] = make_float4(acc[12], acc[13], acc[14], acc[15]);
    }
}

// ---------------------------------------------------------------------------
// Launch
// Inputs (metadata order): input, boundary, edge_list, edge_weight,
//                          relation_weight, W, b
// ---------------------------------------------------------------------------
extern "C" void kernel_launch(void* const* d_in, const int* in_sizes, int n_in,
                              void* d_out, int out_size)
{
    const float* input    = (const float*)d_in[0];
    const float* boundary = (const float*)d_in[1];
    const int*   edges    = (const int*)  d_in[2];
    const float* eweight  = (const float*)d_in[3];
    const float* relw     = (const float*)d_in[4];
    const float* W        = (const float*)d_in[5];
    const float* b        = (const float*)d_in[6];
    float*       out      = (float*)d_out;

    hist_kernel<<<((NUM_EDGE + 3) / 4 + 255) / 256, 256>>>(edges);
    scan_kernel<<<1, SCAN_T>>>();
    scatter_kernel<<<(NUM_EDGE + 255) / 256, 256>>>(edges, eweight);
    gather_gemm_kernel<<<(NUM_NODE + 63) / 64, 256>>>(
        input, boundary, relw, W, b, out);
}

// round 16
// speedup vs baseline: 1.2526x; 1.0068x over previous
#include <cuda_runtime.h>
#include <cstdint>

#define NUM_NODE 50000
#define NUM_EDGE 1600000
#define NUM_REL  512
#define DIM      64
#define SCAN_T   1024

// ---------------------------------------------------------------------------
// Device scratch (alloc-free rule: __device__ globals).
// g_count zero-init at load; gather_gemm re-zeroes per call.
// ---------------------------------------------------------------------------
__device__ int   g_count[NUM_NODE];
__device__ int   g_off[NUM_NODE + 1];
__device__ int   g_pos[NUM_EDGE];      // intra-bucket position per edge
__device__ int2  g_meta[NUM_EDGE];     // (u | r<<16 | nl<<25, w_bits)

// ---------------------------------------------------------------------------
// K1: histogram + per-edge bucket position (4 edges/thread, int4 loads)
// ---------------------------------------------------------------------------
__global__ void __launch_bounds__(256) hist_kernel(const int* __restrict__ edge_list) {
    int t  = blockIdx.x * blockDim.x + threadIdx.x;
    int e0 = t * 4;
    if (e0 >= NUM_EDGE) return;

    if (e0 + 4 <= NUM_EDGE) {
        const int4* el = (const int4*)(edge_list + (size_t)e0 * 3);
        int4 c0 = __ldg(&el[0]);   // u0 v0 r0 u1
        int4 c1 = __ldg(&el[1]);   // v1 r1 u2 v2
        int4 c2 = __ldg(&el[2]);   // r2 u3 v3 r3
        int4 p;
        p.x = atomicAdd(&g_count[c0.y], 1);
        p.y = atomicAdd(&g_count[c1.x], 1);
        p.z = atomicAdd(&g_count[c1.w], 1);
        p.w = atomicAdd(&g_count[c2.z], 1);
        *((int4*)(g_pos + e0)) = p;
    } else {
        for (int e = e0; e < NUM_EDGE; e++) {
            int v = __ldg(&edge_list[e * 3 + 1]);
            g_pos[e] = atomicAdd(&g_count[v], 1);
        }
    }
}

// ---------------------------------------------------------------------------
// K2: single-block exclusive scan, warp-coalesced two-pass
// ---------------------------------------------------------------------------
__global__ void __launch_bounds__(SCAN_T) scan_kernel() {
    __shared__ int wsum[32];
    int t    = threadIdx.x;
    int wid  = t >> 5;
    int lane = t & 31;
    const int CHW = (NUM_NODE + 31) / 32;
    int base = wid * CHW;
    int end  = min(base + CHW, NUM_NODE);

    int sum = 0;
    for (int i = base + lane; i < end; i += 32) sum += g_count[i];
    #pragma unroll
    for (int o = 16; o > 0; o >>= 1) sum += __shfl_xor_sync(0xffffffffu, sum, o);
    if (lane == 0) wsum[wid] = sum;
    __syncthreads();

    if (wid == 0) {
        int v    = wsum[lane];
        int incl = v;
        #pragma unroll
        for (int o = 1; o < 32; o <<= 1) {
            int p = __shfl_up_sync(0xffffffffu, incl, o);
            if (lane >= o) incl += p;
        }
        wsum[lane] = incl - v;
        if (lane == 31) g_off[NUM_NODE] = incl;
    }
    __syncthreads();

    int run = wsum[wid];
    for (int i0 = base; i0 < end; i0 += 32) {
        int i = i0 + lane;
        int c = (i < end) ? g_count[i] : 0;
        int incl = c;
        #pragma unroll
        for (int o = 1; o < 32; o <<= 1) {
            int p = __shfl_up_sync(0xffffffffu, incl, o);
            if (lane >= o) incl += p;
        }
        if (i < end) g_off[i] = run + incl - c;
        run += __shfl_sync(0xffffffffu, incl, 31);
    }
}

// ---------------------------------------------------------------------------
// K3: scatter packed edge meta into buckets — packs nl = v & 63 into bits 25-30
// ---------------------------------------------------------------------------
__global__ void __launch_bounds__(256) scatter_kernel(
    const int*   __restrict__ edge_list,
    const float* __restrict__ edge_weight)
{
    int e = blockIdx.x * blockDim.x + threadIdx.x;
    if (e < NUM_EDGE) {
        int   u   = __ldg(&edge_list[e * 3 + 0]);
        int   v   = __ldg(&edge_list[e * 3 + 1]);
        int   r   = __ldg(&edge_list[e * 3 + 2]);
        float w   = __ldg(&edge_weight[e]);
        int   pos = __ldg(&g_pos[e]);
        int  slot = __ldg(&g_off[v]) + pos;
        int  key  = u | (r << 16) | ((v & 63) << 25);
        g_meta[slot] = make_int2(key, __float_as_int(w));
    }
}

// ---------------------------------------------------------------------------
// K4: fused edge-stream gather + variance + 64x64 GEMM.
// Block = 256 threads owns 64-node tile AND its contiguous edge range.
// 16 half-warp streams walk contiguous edge chunks (unroll 4 + meta
// prefetch), register-accumulating per dest run, flushing on nl-change
// via smem atomicAdd. No per-node pipeline drains.
// ---------------------------------------------------------------------------
__global__ void __launch_bounds__(256, 4) gather_gemm_kernel(
    const float* __restrict__ input,
    const float* __restrict__ boundary,
    const float* __restrict__ relw,
    const float* __restrict__ W,
    const float* __restrict__ b,
    float* __restrict__ out)
{
    __shared__ float Ssh[64 * 68];     // s accumulators -> u (in place)
    __shared__ float Qsh[64 * 68];     // q accumulators -> reused as Wsh
    __shared__ float bsh[DIM];
    __shared__ float dinv[64];

    int tid  = threadIdx.x;
    int wid  = tid >> 5;
    int lane = tid & 31;
    int g    = lane >> 4;        // half-warp id within warp
    int sub  = lane & 15;        // float4 slice of 64-dim row
    int n0   = blockIdx.x * 64;

    // Init accumulators from boundary (coalesced)
    for (int i = tid; i < 64 * DIM; i += 256) {
        int nl = i >> 6, d = i & 63;
        int n  = n0 + nl;
        float bv = (n < NUM_NODE) ? __ldg(&boundary[(size_t)n0 * DIM + i]) : 0.0f;
        Ssh[nl * 68 + d] = bv;
        Qsh[nl * 68 + d] = bv * bv;
    }
    if (tid < 64) {
        int n = n0 + tid;
        if (n < NUM_NODE) {
            int st = __ldg(&g_off[n]);
            int en = __ldg(&g_off[n + 1]);
            dinv[tid] = 1.0f / ((float)(en - st) + 1.0f);
            g_count[n] = 0;      // self-clean for next call
        } else {
            dinv[tid] = 0.0f;
        }
        if (tid == 0) bsh[0] = 0.0f;   // no-op keep
    }
    if (tid < DIM) bsh[tid] = __ldg(&b[tid]);
    __syncthreads();

    // Edge range for this tile
    int nend   = (n0 + 64 < NUM_NODE) ? (n0 + 64) : NUM_NODE;
    int estart = __ldg(&g_off[n0]);
    int eend   = __ldg(&g_off[nend]);
    int cnt    = eend - estart;

    int h  = (wid << 1) | g;              // 0..15 stream id
    int C  = (cnt + 15) >> 4;             // chunk per stream
    int jb = estart + h * C;
    int je = jb + C; if (je > eend) je = eend;

    float4 sa = make_float4(0.f, 0.f, 0.f, 0.f);
    float4 qa = make_float4(0.f, 0.f, 0.f, 0.f);
    int cur = -1;

#define FLUSH() do {                                                     \
        float* sp_ = &Ssh[cur * 68 + (sub << 2)];                        \
        float* qp_ = &Qsh[cur * 68 + (sub << 2)];                        \
        atomicAdd(sp_ + 0, sa.x); atomicAdd(sp_ + 1, sa.y);              \
        atomicAdd(sp_ + 2, sa.z); atomicAdd(sp_ + 3, sa.w);              \
        atomicAdd(qp_ + 0, qa.x); atomicAdd(qp_ + 1, qa.y);              \
        atomicAdd(qp_ + 2, qa.z); atomicAdd(qp_ + 3, qa.w);              \
        sa = make_float4(0.f, 0.f, 0.f, 0.f);                            \
        qa = make_float4(0.f, 0.f, 0.f, 0.f);                            \
    } while (0)

#define ACC(a_, nl_) do {                                                \
        if ((nl_) != cur) { if (cur >= 0) FLUSH(); cur = (nl_); }        \
        sa.x += (a_).x; sa.y += (a_).y; sa.z += (a_).z; sa.w += (a_).w;  \
        qa.x += (a_).x * (a_).x; qa.y += (a_).y * (a_).y;                \
        qa.z += (a_).z * (a_).z; qa.w += (a_).w * (a_).w;                \
    } while (0)

    int j   = jb;
    int lim = je - 4;

    if (j <= lim) {
        int2 m0 = __ldg(&g_meta[j + 0]);
        int2 m1 = __ldg(&g_meta[j + 1]);
        int2 m2 = __ldg(&g_meta[j + 2]);
        int2 m3 = __ldg(&g_meta[j + 3]);

        #pragma unroll 1
        for (; j <= lim; j += 4) {
            // Data loads for current metas
            float4 x0 = __ldg((const float4*)(input + (size_t)(m0.x & 0xFFFF) * DIM) + sub);
            float4 x1 = __ldg((const float4*)(input + (size_t)(m1.x & 0xFFFF) * DIM) + sub);
            float4 x2 = __ldg((const float4*)(input + (size_t)(m2.x & 0xFFFF) * DIM) + sub);
            float4 x3 = __ldg((const float4*)(input + (size_t)(m3.x & 0xFFFF) * DIM) + sub);

            float4 r0 = __ldg((const float4*)(relw + (size_t)((m0.x >> 16) & 0x1FF) * DIM) + sub);
            float4 r1 = __ldg((const float4*)(relw + (size_t)((m1.x >> 16) & 0x1FF) * DIM) + sub);
            float4 r2 = __ldg((const float4*)(relw + (size_t)((m2.x >> 16) & 0x1FF) * DIM) + sub);
            float4 r3 = __ldg((const float4*)(relw + (size_t)((m3.x >> 16) & 0x1FF) * DIM) + sub);

            // Prefetch next batch metas (sequential addresses)
            int jn = (j + 4 <= lim) ? (j + 4) : j;
            int2 t0 = __ldg(&g_meta[jn + 0]);
            int2 t1 = __ldg(&g_meta[jn + 1]);
            int2 t2 = __ldg(&g_meta[jn + 2]);
            int2 t3 = __ldg(&g_meta[jn + 3]);

            int nl0 = ((unsigned)m0.x) >> 25;
            int nl1 = ((unsigned)m1.x) >> 25;
            int nl2 = ((unsigned)m2.x) >> 25;
            int nl3 = ((unsigned)m3.x) >> 25;

            float w0 = __int_as_float(m0.y);
            float w1 = __int_as_float(m1.y);
            float w2 = __int_as_float(m2.y);
            float w3 = __int_as_float(m3.y);

            float4 a0, a1, a2, a3;
            a0.x = x0.x * r0.x * w0; a0.y = x0.y * r0.y * w0;
            a0.z = x0.z * r0.z * w0; a0.w = x0.w * r0.w * w0;
            a1.x = x1.x * r1.x * w1; a1.y = x1.y * r1.y * w1;
            a1.z = x1.z * r1.z * w1; a1.w = x1.w * r1.w * w1;
            a2.x = x2.x * r2.x * w2; a2.y = x2.y * r2.y * w2;
            a2.z = x2.z * r2.z * w2; a2.w = x2.w * r2.w * w2;
            a3.x = x3.x * r3.x * w3; a3.y = x3.y * r3.y * w3;
            a3.z = x3.z * r3.z * w3; a3.w = x3.w * r3.w * w3;

            if (nl0 == cur && nl1 == nl0 && nl2 == nl0 && nl3 == nl0) {
                // Fast path: whole batch same dest as current run
                sa.x += a0.x + a1.x + a2.x + a3.x;
                sa.y += a0.y + a1.y + a2.y + a3.y;
                sa.z += a0.z + a1.z + a2.z + a3.z;
                sa.w += a0.w + a1.w + a2.w + a3.w;
                qa.x += a0.x * a0.x + a1.x * a1.x + a2.x * a2.x + a3.x * a3.x;
                qa.y += a0.y * a0.y + a1.y * a1.y + a2.y * a2.y + a3.y * a3.y;
                qa.z += a0.z * a0.z + a1.z * a1.z + a2.z * a2.z + a3.z * a3.z;
                qa.w += a0.w * a0.w + a1.w * a1.w + a2.w * a2.w + a3.w * a3.w;
            } else {
                ACC(a0, nl0); ACC(a1, nl1); ACC(a2, nl2); ACC(a3, nl3);
            }

            m0 = t0; m1 = t1; m2 = t2; m3 = t3;
        }
    }

    // Remainder edges
    for (; j < je; j++) {
        int2 m = __ldg(&g_meta[j]);
        int nl    = ((unsigned)m.x) >> 25;
        float w   = __int_as_float(m.y);
        float4 x  = __ldg((const float4*)(input + (size_t)(m.x & 0xFFFF) * DIM) + sub);
        float4 rr = __ldg((const float4*)(relw  + (size_t)((m.x >> 16) & 0x1FF) * DIM) + sub);
        float4 a;
        a.x = x.x * rr.x * w; a.y = x.y * rr.y * w;
        a.z = x.z * rr.z * w; a.w = x.w * rr.w * w;
        ACC(a, nl);
    }
    if (cur >= 0) FLUSH();
    __syncthreads();

    // ---- Variance: u = sqrt(max(q/d1 - (s/d1)^2, 1e-6)), in place into Ssh ----
    for (int i = tid; i < 64 * DIM; i += 256) {
        int nl = i >> 6, d = i & 63;
        float inv = dinv[nl];
        float s  = Ssh[nl * 68 + d];
        float q  = Qsh[nl * 68 + d];
        float sm = s * inv;
        Ssh[nl * 68 + d] = sqrtf(fmaxf(q * inv - sm * sm, 1e-6f));
    }
    __syncthreads();

    // ---- Load W transposed into Qsh storage (now free) ----
    float* Wsh = Qsh;
    for (int i = tid; i < DIM * DIM; i += 256) {
        int jj = i >> 6, d = i & 63;
        Wsh[d * DIM + jj] = __ldg(&W[i]);
    }
    __syncthreads();

    // ---- GEMM: out = u @ W^T + b ----
    int nl = tid >> 2;
    int j0 = (tid & 3) * 16;

    float acc[16];
    #pragma unroll
    for (int k = 0; k < 16; k++) acc[k] = bsh[j0 + k];

    #pragma unroll 4
    for (int d = 0; d < DIM; d++) {
        float u = Ssh[nl * 68 + d];
        const float4* wrow = (const float4*)&Wsh[d * DIM + j0];
        float4 w0 = wrow[0];
        float4 w1 = wrow[1];
        float4 w2 = wrow[2];
        float4 w3 = wrow[3];
        acc[0]  += u * w0.x;  acc[1]  += u * w0.y;
        acc[2]  += u * w0.z;  acc[3]  += u * w0.w;
        acc[4]  += u * w1.x;  acc[5]  += u * w1.y;
        acc[6]  += u * w1.z;  acc[7]  += u * w1.w;
        acc[8]  += u * w2.x;  acc[9]  += u * w2.y;
        acc[10] += u * w2.z;  acc[11] += u * w2.w;
        acc[12] += u * w3.x;  acc[13] += u * w3.y;
        acc[14] += u * w3.z;  acc[15] += u * w3.w;
    }

    int n = n0 + nl;
    if (n < NUM_NODE) {
        float4* op = (float4*)(out + (size_t)n * DIM + j0);
        op[0] = make_float4(acc[0],  acc[1],  acc[2],  acc[3]);
        op[1] = make_float4(acc[4],  acc[5],  acc[6],  acc[7]);
        op[2] = make_float4(acc[8],  acc[9],  acc[10], acc[11]);
        op[3] = make_float4(acc[12], acc[13], acc[14], acc[15]);
    }
}

// ---------------------------------------------------------------------------
// Launch. Inputs: input, boundary, edge_list, edge_weight, relation_weight, W, b
// ---------------------------------------------------------------------------
extern "C" void kernel_launch(void* const* d_in, const int* in_sizes, int n_in,
                              void* d_out, int out_size)
{
    const float* input    = (const float*)d_in[0];
    const float* boundary = (const float*)d_in[1];
    const int*   edges    = (const int*)  d_in[2];
    const float* eweight  = (const float*)d_in[3];
    const float* relw     = (const float*)d_in[4];
    const float* W        = (const float*)d_in[5];
    const float* b        = (const float*)d_in[6];
    float*       out      = (float*)d_out;

    hist_kernel<<<((NUM_EDGE + 3) / 4 + 255) / 256, 256>>>(edges);
    scan_kernel<<<1, SCAN_T>>>();
    scatter_kernel<<<(NUM_EDGE + 255) / 256, 256>>>(edges, eweight);
    gather_gemm_kernel<<<(NUM_NODE + 63) / 64, 256>>>(
        input, boundary, relw, W, b, out);
}